// round 4
// baseline (speedup 1.0000x reference)
#include <cuda_runtime.h>
#include <cstdint>

#define TILE       256
#define BLOCK_T    256
#define STAGES     2
#define F4_PER_TILE (TILE * 25)                   // 6400 float4
#define TILE_BYTES  (F4_PER_TILE * 16)            // 102400
#define SMEM_BYTES  (STAGES * TILE_BYTES)         // 204800

__device__ __forceinline__ void mbar_wait(unsigned mbar, unsigned phase) {
    unsigned done;
    asm volatile("{\n\t.reg .pred p;\n\t"
                 "mbarrier.try_wait.parity.acquire.cta.shared::cta.b64 p, [%1], %2;\n\t"
                 "selp.b32 %0, 1, 0, p;\n\t}"
                 : "=r"(done) : "r"(mbar), "r"(phase) : "memory");
    while (!done) {
        asm volatile("{\n\t.reg .pred p;\n\t"
                     "mbarrier.try_wait.parity.acquire.cta.shared::cta.b64 p, [%1], %2, 0x989680;\n\t"
                     "selp.b32 %0, 1, 0, p;\n\t}"
                     : "=r"(done) : "r"(mbar), "r"(phase) : "memory");
    }
}

__device__ __forceinline__ void issue_tile(const float* __restrict__ x,
                                           float4* sx_stage, unsigned mbar,
                                           int t, int batch) {
    int rows = batch - t * TILE;
    if (rows > TILE) rows = TILE;
    unsigned bytes = (unsigned)rows * 400u;
    asm volatile("mbarrier.arrive.expect_tx.shared.b64 _, [%0], %1;"
                 :: "r"(mbar), "r"(bytes) : "memory");
    unsigned dst = (unsigned)__cvta_generic_to_shared(sx_stage);
    const float* src = x + (size_t)t * (TILE * 100);
    asm volatile("cp.async.bulk.shared::cta.global.mbarrier::complete_tx::bytes "
                 "[%0], [%1], %2, [%3];"
                 :: "r"(dst), "l"(src), "r"(bytes), "r"(mbar) : "memory");
}

__global__ void __launch_bounds__(BLOCK_T, 1) fused_kernel(
    const float* __restrict__ x,
    const float* __restrict__ A_real,
    const float* __restrict__ A_imag,
    const float* __restrict__ psi_real,
    const float* __restrict__ psi_imag,
    float2* __restrict__ out,
    int batch, int ntiles)
{
    extern __shared__ __align__(128) float4 sx[];       // [STAGES][F4_PER_TILE]
    __shared__ __align__(16) float sMf[200];
    __shared__ __align__(8) unsigned long long mbar_store[STAGES];

    int tid = threadIdx.x;
    unsigned mbar0 = (unsigned)__cvta_generic_to_shared(&mbar_store[0]);

    if (tid == 0) {
        #pragma unroll
        for (int s = 0; s < STAGES; s++)
            asm volatile("mbarrier.init.shared.b64 [%0], %1;"
                         :: "r"(mbar0 + s * 8), "r"(1) : "memory");
    }
    __syncthreads();

    int nblk  = gridDim.x;
    int first = blockIdx.x;

    // Prologue: enqueue up to STAGES tiles on the copy engine.
    if (tid == 0) {
        #pragma unroll
        for (int s = 0; s < STAGES; s++) {
            int t = first + s * nblk;
            if (t < ntiles)
                issue_tile(x, sx + s * F4_PER_TILE, mbar0 + s * 8, t, batch);
        }
    }

    // Compute M = sum_ij (P_re A_real - P_im A_imag) — hidden under the first
    // TMA flight. A is L2-hot (all blocks read the same 160KB).
    if (tid < 200) {
        int k = tid / 100, a = tid - k * 100;
        float pr[10], pi[10];
        #pragma unroll
        for (int q = 0; q < 10; q++) { pr[q] = psi_real[q]; pi[q] = psi_imag[q]; }
        float acc = 0.0f;
        #pragma unroll
        for (int i = 0; i < 10; i++) {
            #pragma unroll
            for (int j = 0; j < 10; j++) {
                float Pre = pr[i] * pr[j] + pi[i] * pi[j];
                float Pim = pr[i] * pi[j] - pi[i] * pr[j];
                int idx = ((k * 10 + i) * 10 + j) * 100 + a;
                acc = fmaf(Pre, A_real[idx], acc);
                acc = fmaf(-Pim, A_imag[idx], acc);
            }
        }
        sMf[tid] = acc;
    }
    __syncthreads();

    const float4* sM4 = reinterpret_cast<const float4*>(sMf);   // [50]

    int cnt = 0;
    for (int t = first; t < ntiles; t += nblk, cnt++) {
        int s = cnt & 1;                    // STAGES == 2
        unsigned phase = (cnt >> 1) & 1;
        mbar_wait(mbar0 + s * 8, phase);

        int row = t * TILE + tid;
        if (row < batch) {
            const float4* xr = sx + s * F4_PER_TILE + tid * 25;
            float s0 = 0.0f, s1 = 0.0f;
            #pragma unroll
            for (int i = 0; i < 25; i++) {
                float4 v  = xr[i];
                float4 m0 = sM4[i];
                float4 m1 = sM4[25 + i];
                s0 = fmaf(v.x, m0.x, s0); s0 = fmaf(v.y, m0.y, s0);
                s0 = fmaf(v.z, m0.z, s0); s0 = fmaf(v.w, m0.w, s0);
                s1 = fmaf(v.x, m1.x, s1); s1 = fmaf(v.y, m1.y, s1);
                s1 = fmaf(v.z, m1.z, s1); s1 = fmaf(v.w, m1.w, s1);
            }
            out[row] = make_float2(s0, s1);
        }
        __syncthreads();                    // all threads done reading stage s

        int tn = t + STAGES * nblk;
        if (tid == 0 && tn < ntiles)
            issue_tile(x, sx + s * F4_PER_TILE, mbar0 + s * 8, tn, batch);
    }
}

extern "C" void kernel_launch(void* const* d_in, const int* in_sizes, int n_in,
                              void* d_out, int out_size) {
    const float* x        = (const float*)d_in[0];  // [BATCH, 100]
    const float* A_real   = (const float*)d_in[1];  // [2,10,10,100]
    const float* A_imag   = (const float*)d_in[2];  // [2,10,10,100]
    const float* psi_real = (const float*)d_in[3];  // [10]
    const float* psi_imag = (const float*)d_in[4];  // [10]

    int batch  = in_sizes[0] / 100;
    int ntiles = (batch + TILE - 1) / TILE;

    static bool attr_done = false;
    if (!attr_done) {
        cudaFuncSetAttribute(fused_kernel,
                             cudaFuncAttributeMaxDynamicSharedMemorySize, SMEM_BYTES);
        attr_done = true;
    }

    int nblk = 148;
    if (nblk > ntiles) nblk = ntiles;
    fused_kernel<<<nblk, BLOCK_T, SMEM_BYTES>>>(x, A_real, A_imag,
                                                psi_real, psi_imag,
                                                reinterpret_cast<float2*>(d_out),
                                                batch, ntiles);
}